// round 9
// baseline (speedup 1.0000x reference)
#include <cuda_runtime.h>
#include <cuda_bf16.h>
#include <math.h>
#include <stdint.h>

// Problem constants
#define Bc  4
#define Tc  4096
#define Dc  1024
#define Hc  16
#define HDc 64
#define Kc  32

#define NS1 64      // t-slices for xs build
#define SKS 16      // split-K for spec GEMM (slab 64)
#define SKZ 16      // split-K for Z GEMM   (slab 64)

// ---------------- scratch (static device arrays) ----------------
__device__ float g_xs_p[NS1 * 128 * 1024];       // xs partials
__device__ float g_xm_p[NS1 * Bc * 1024];        // xmean partials
__device__ float g_xm[Bc * 1024];                // sum_t x
__device__ float g_qm[Bc * 1024];                // xm @ Wq^T (unnormalized)
__device__ float g_spec_p[SKS * 128 * 3072];     // spec GEMM partials
__device__ float g_Zp[SKZ * 128 * 1024];         // Z GEMM partials
__device__ float g_Z[128 * 1024];                // ws2 @ W_out^T
__device__ __nv_bfloat16 g_xshi[128 * 1024], g_xslo[128 * 1024];
__device__ __nv_bfloat16 g_wqhi[3 * 1024 * 1024], g_wqlo[3 * 1024 * 1024];
__device__ __nv_bfloat16 g_wohi[1024 * 1024], g_wolo[1024 * 1024];
__device__ __nv_bfloat16 g_wshi[128 * 1024], g_wslo[128 * 1024];

__device__ __forceinline__ uint32_t smem_u32(const void* p) {
    uint32_t a;
    asm("{ .reg .u64 t; cvta.to.shared.u64 t, %1; cvt.u32.u64 %0, t; }"
        : "=r"(a) : "l"(p));
    return a;
}
__device__ __forceinline__ uint2 pack_hilo4(const float* v, bool lo) {
    __nv_bfloat16 h[4];
#pragma unroll
    for (int j = 0; j < 4; j++) {
        __nv_bfloat16 hh = __float2bfloat16_rn(v[j]);
        h[j] = lo ? __float2bfloat16_rn(v[j] - __bfloat162float(hh)) : hh;
    }
    uint2 r;
    r.x = (uint32_t)__bfloat16_as_ushort(h[0]) |
          ((uint32_t)__bfloat16_as_ushort(h[1]) << 16);
    r.y = (uint32_t)__bfloat16_as_ushort(h[2]) |
          ((uint32_t)__bfloat16_as_ushort(h[3]) << 16);
    return r;
}

// ---------------------------------------------------------------------------
// K1: xs partials + xm partials.  grid (b=4, slice=64), 256 threads.
// ---------------------------------------------------------------------------
__global__ __launch_bounds__(256) void xs_part_kernel(
    const float* __restrict__ x, const float* __restrict__ sb)
{
    const int b = blockIdx.x, s = blockIdx.y;
    const int tid = threadIdx.x;
    const int d0 = tid * 4;
    const int t0 = s * 64;

    __shared__ __align__(16) float sbs[64][32];
    {
        int e = tid;
#pragma unroll
        for (int i = 0; i < 2; i++, e += 256) {
            int tt = e >> 3, k4 = (e & 7) * 4;
            *(float4*)&sbs[tt][k4] =
                *(const float4*)(sb + ((size_t)b * Tc + t0 + tt) * 32 + k4);
        }
    }
    __syncthreads();

    float acc[32][4];
#pragma unroll
    for (int k = 0; k < 32; k++)
#pragma unroll
        for (int j = 0; j < 4; j++) acc[k][j] = 0.f;
    float am[4] = {0.f, 0.f, 0.f, 0.f};

    const float* xb = x + ((size_t)b * Tc + t0) * Dc + d0;
    for (int t = 0; t < 64; t++) {
        float4 xv = *(const float4*)(xb + (size_t)t * Dc);
        float v[4] = { xv.x, xv.y, xv.z, xv.w };
#pragma unroll
        for (int j = 0; j < 4; j++) am[j] += v[j];
#pragma unroll
        for (int k8 = 0; k8 < 8; k8++) {
            float4 sv = *(const float4*)&sbs[t][k8 * 4];
            float sk[4] = { sv.x, sv.y, sv.z, sv.w };
#pragma unroll
            for (int ki = 0; ki < 4; ki++)
#pragma unroll
                for (int j = 0; j < 4; j++)
                    acc[k8 * 4 + ki][j] = fmaf(sk[ki], v[j], acc[k8 * 4 + ki][j]);
        }
    }

    float* op = g_xs_p + (size_t)s * 131072 + (size_t)b * 32 * 1024 + d0;
#pragma unroll
    for (int k = 0; k < 32; k++)
        *(float4*)(op + k * 1024) = make_float4(acc[k][0], acc[k][1],
                                                acc[k][2], acc[k][3]);
    *(float4*)(g_xm_p + (size_t)s * 4096 + b * 1024 + d0) =
        make_float4(am[0], am[1], am[2], am[3]);
}

// ---------------------------------------------------------------------------
// Reduce xs partials -> bf16 hi/lo; xm partials -> fp32.
// ---------------------------------------------------------------------------
__global__ void reduce_xs_xm()
{
    int i = blockIdx.x * blockDim.x + threadIdx.x;
    if (i < 32768) {
        float4 a = make_float4(0.f, 0.f, 0.f, 0.f);
#pragma unroll 4
        for (int s = 0; s < NS1; s++) {
            float4 v = ((const float4*)g_xs_p)[(size_t)s * 32768 + i];
            a.x += v.x; a.y += v.y; a.z += v.z; a.w += v.w;
        }
        float vv[4] = { a.x, a.y, a.z, a.w };
        ((uint2*)g_xshi)[i] = pack_hilo4(vv, false);
        ((uint2*)g_xslo)[i] = pack_hilo4(vv, true);
    } else if (i < 32768 + 1024) {
        int j = i - 32768;
        float4 a = make_float4(0.f, 0.f, 0.f, 0.f);
#pragma unroll 4
        for (int s = 0; s < NS1; s++) {
            float4 v = ((const float4*)g_xm_p)[(size_t)s * 1024 + j];
            a.x += v.x; a.y += v.y; a.z += v.z; a.w += v.w;
        }
        ((float4*)g_xm)[j] = a;
    }
}

// ---------------------------------------------------------------------------
// Split Wqkv (3M) and Wout (1M) into bf16 hi/lo. 4 elems/thread.
// ---------------------------------------------------------------------------
__global__ void split_w_kernel(const float* __restrict__ Wqkv,
                               const float* __restrict__ Wout)
{
    int i = blockIdx.x * blockDim.x + threadIdx.x;
    const int NQ4 = 3 * 1024 * 1024 / 4;
    const float* src;
    __nv_bfloat16 *hi, *lo;
    int j;
    if (i < NQ4) { src = Wqkv; hi = g_wqhi; lo = g_wqlo; j = i; }
    else { src = Wout; hi = g_wohi; lo = g_wolo; j = i - NQ4;
           if (j >= 1024 * 1024 / 4) return; }
    float4 v = ((const float4*)src)[j];
    float vv[4] = { v.x, v.y, v.z, v.w };
    ((uint2*)hi)[j] = pack_hilo4(vv, false);
    ((uint2*)lo)[j] = pack_hilo4(vv, true);
}

// ---------------------------------------------------------------------------
// HMMA GEMM NT, M=128 fixed, split-K (slab = 64 = 2 K-tiles of 32):
// Cp[z][m][n] = sum_{k in slab z} (Ahi*Bhi + Ahi*Blo + Alo*Bhi)
// 128x128 tile, cp.async double buffer, 8 warps (2x4), warp 64x32, m16n8k16.
// ---------------------------------------------------------------------------
#define KT      32
#define RB      80
#define TILE_B  (128 * RB)
#define STAGE_B (4 * TILE_B)

__global__ void __launch_bounds__(256) gemm_mma_sk(
    const __nv_bfloat16* __restrict__ Ahi, const __nv_bfloat16* __restrict__ Alo,
    const __nv_bfloat16* __restrict__ Bhi, const __nv_bfloat16* __restrict__ Blo,
    float* __restrict__ Cp, int N, int kPerSplit)
{
    extern __shared__ char smem[];
    const int Kd = 1024;
    const uint32_t sbase = smem_u32(smem);
    const int tid = threadIdx.x, wid = tid >> 5, lane = tid & 31;
    const int col0 = blockIdx.x * 128;
    const int kb = blockIdx.z * kPerSplit;
    const int wm = wid >> 2, wn = wid & 3;

    const __nv_bfloat16* s0 = Ahi + kb;
    const __nv_bfloat16* s1 = Alo + kb;
    const __nv_bfloat16* s2 = Bhi + (size_t)col0 * Kd + kb;
    const __nv_bfloat16* s3 = Blo + (size_t)col0 * Kd + kb;

    const int e0 = tid, e1 = tid + 256;
    const int r0c = e0 >> 2, c0c = e0 & 3;
    const int r1c = e1 >> 2, c1c = e1 & 3;

#define LOAD_STAGE(kt, buf)                                                   \
    do {                                                                      \
        uint32_t db = sbase + (buf) * STAGE_B;                                \
        const __nv_bfloat16* srcs[4] = { s0, s1, s2, s3 };                    \
        _Pragma("unroll")                                                     \
        for (int a = 0; a < 4; a++) {                                         \
            const char* g0 = (const char*)(srcs[a] + (size_t)r0c * Kd + (kt) * KT) + c0c * 16; \
            const char* g1 = (const char*)(srcs[a] + (size_t)r1c * Kd + (kt) * KT) + c1c * 16; \
            uint32_t p0 = db + a * TILE_B + r0c * RB + c0c * 16;              \
            uint32_t p1 = db + a * TILE_B + r1c * RB + c1c * 16;              \
            asm volatile("cp.async.cg.shared.global [%0],[%1],16;" :: "r"(p0), "l"(g0)); \
            asm volatile("cp.async.cg.shared.global [%0],[%1],16;" :: "r"(p1), "l"(g1)); \
        }                                                                     \
        asm volatile("cp.async.commit_group;");                               \
    } while (0)

    float acc[4][4][4];
#pragma unroll
    for (int i = 0; i < 4; i++)
#pragma unroll
        for (int j = 0; j < 4; j++)
#pragma unroll
            for (int q = 0; q < 4; q++) acc[i][j][q] = 0.f;

    LOAD_STAGE(0, 0);
    int buf = 0;
    const int nTiles = kPerSplit / KT;

    for (int kt = 0; kt < nTiles; kt++) {
        asm volatile("cp.async.wait_group 0;");
        __syncthreads();
        if (kt + 1 < nTiles) LOAD_STAGE(kt + 1, buf ^ 1);

        const uint32_t db = sbase + buf * STAGE_B;
#pragma unroll
        for (int ks = 0; ks < 2; ks++) {
            uint32_t rah[4][4], ral[4][4];
#pragma unroll
            for (int mf = 0; mf < 4; mf++) {
                int r = wm * 64 + mf * 16 + (lane & 15);
                uint32_t ad = db + r * RB + ks * 32 + ((lane >> 4) & 1) * 16;
                asm volatile("ldmatrix.sync.aligned.m8n8.x4.shared.b16 {%0,%1,%2,%3},[%4];"
                    : "=r"(rah[mf][0]), "=r"(rah[mf][1]), "=r"(rah[mf][2]), "=r"(rah[mf][3])
                    : "r"(ad));
                asm volatile("ldmatrix.sync.aligned.m8n8.x4.shared.b16 {%0,%1,%2,%3},[%4];"
                    : "=r"(ral[mf][0]), "=r"(ral[mf][1]), "=r"(ral[mf][2]), "=r"(ral[mf][3])
                    : "r"(ad + TILE_B));
            }
            uint32_t rbh[2][4], rbl[2][4];
#pragma unroll
            for (int np = 0; np < 2; np++) {
                int r = wn * 32 + (np * 2 + (lane >> 4)) * 8 + (lane & 7);
                uint32_t bd = db + 2 * TILE_B + r * RB + ks * 32 + ((lane >> 3) & 1) * 16;
                asm volatile("ldmatrix.sync.aligned.m8n8.x4.shared.b16 {%0,%1,%2,%3},[%4];"
                    : "=r"(rbh[np][0]), "=r"(rbh[np][1]), "=r"(rbh[np][2]), "=r"(rbh[np][3])
                    : "r"(bd));
                asm volatile("ldmatrix.sync.aligned.m8n8.x4.shared.b16 {%0,%1,%2,%3},[%4];"
                    : "=r"(rbl[np][0]), "=r"(rbl[np][1]), "=r"(rbl[np][2]), "=r"(rbl[np][3])
                    : "r"(bd + TILE_B));
            }
#define MMA(d, A, b0, b1)                                                     \
    asm volatile("mma.sync.aligned.m16n8k16.row.col.f32.bf16.bf16.f32 "       \
                 "{%0,%1,%2,%3},{%4,%5,%6,%7},{%8,%9},{%0,%1,%2,%3};"         \
                 : "+f"(d[0]), "+f"(d[1]), "+f"(d[2]), "+f"(d[3])             \
                 : "r"(A[0]), "r"(A[1]), "r"(A[2]), "r"(A[3]),                \
                   "r"(b0), "r"(b1))
#pragma unroll
            for (int mf = 0; mf < 4; mf++)
#pragma unroll
                for (int nf = 0; nf < 4; nf++)
                    MMA(acc[mf][nf], rah[mf], rbh[nf >> 1][(nf & 1) * 2],
                        rbh[nf >> 1][(nf & 1) * 2 + 1]);
#pragma unroll
            for (int mf = 0; mf < 4; mf++)
#pragma unroll
                for (int nf = 0; nf < 4; nf++)
                    MMA(acc[mf][nf], rah[mf], rbl[nf >> 1][(nf & 1) * 2],
                        rbl[nf >> 1][(nf & 1) * 2 + 1]);
#pragma unroll
            for (int mf = 0; mf < 4; mf++)
#pragma unroll
                for (int nf = 0; nf < 4; nf++)
                    MMA(acc[mf][nf], ral[mf], rbh[nf >> 1][(nf & 1) * 2],
                        rbh[nf >> 1][(nf & 1) * 2 + 1]);
#undef MMA
        }
        __syncthreads();
        buf ^= 1;
    }

    float* C = Cp + (size_t)blockIdx.z * 128 * N;
    const int mrow = lane >> 2, ncol = (lane & 3) * 2;
#pragma unroll
    for (int mf = 0; mf < 4; mf++) {
#pragma unroll
        for (int nf = 0; nf < 4; nf++) {
            int r  = wm * 64 + mf * 16 + mrow;
            int cc = col0 + wn * 32 + nf * 8 + ncol;
            *(float2*)(C + (size_t)r * N + cc) =
                make_float2(acc[mf][nf][0], acc[mf][nf][1]);
            *(float2*)(C + (size_t)(r + 8) * N + cc) =
                make_float2(acc[mf][nf][2], acc[mf][nf][3]);
        }
    }
#undef LOAD_STAGE
}

// ---------------------------------------------------------------------------
// qm GEMV: g_qm[b*1024+o] = xm[b,:] . Wqkv[o,:]  (warp per output)
// ---------------------------------------------------------------------------
__global__ __launch_bounds__(256) void qm_gemv_kernel(
    const float* __restrict__ Wqkv)
{
    const int w = blockIdx.x * 8 + (threadIdx.x >> 5);
    const int lane = threadIdx.x & 31;
    const int b = w >> 10, o = w & 1023;

    const float4* xm = (const float4*)(g_xm + b * 1024);
    const float4* wr = (const float4*)(Wqkv + (size_t)o * 1024);
    float s = 0.f;
#pragma unroll
    for (int j = 0; j < 8; j++) {
        float4 a = xm[lane + j * 32];
        float4 c = wr[lane + j * 32];
        s = fmaf(a.x, c.x, s); s = fmaf(a.y, c.y, s);
        s = fmaf(a.z, c.z, s); s = fmaf(a.w, c.w, s);
    }
#pragma unroll
    for (int off = 16; off; off >>= 1)
        s += __shfl_down_sync(0xffffffffu, s, off);
    if (lane == 0) g_qm[b * 1024 + o] = s;
}

// ---------------------------------------------------------------------------
// Fused: blocks 0..7: sum spec partials inline + FHN ODE -> response,
//        ws2 (bf16 hi/lo). blocks 8..71: pulse-width MLP.
// ---------------------------------------------------------------------------
__global__ __launch_bounds__(256) void soliton_pulse_kernel(
    const float* __restrict__ d_a, const float* __restrict__ d_b,
    const float* __restrict__ filt,
    const float* __restrict__ W1, const float* __restrict__ b1,
    const float* __restrict__ W2, const float* __restrict__ b2,
    float* __restrict__ out_resp, float* __restrict__ out_pulse)
{
    if (blockIdx.x < 8) {
        const int gid = blockIdx.x * 256 + threadIdx.x;   // 0..2047
        const int m = gid >> 4, h = gid & 15;
        const int b = m >> 5, k = m & 31;
        const size_t rowb = (size_t)m * 3072 + h * 64;    // float index
        const size_t SPL = 128 * 3072;

        // dot = sum_d (sum_s q_p) * (sum_s k_p)
        float dot = 0.f;
#pragma unroll
        for (int d4 = 0; d4 < 16; d4++) {
            float4 q = make_float4(0.f, 0.f, 0.f, 0.f);
            float4 kk = make_float4(0.f, 0.f, 0.f, 0.f);
#pragma unroll
            for (int s = 0; s < SKS; s++) {
                float4 vq = *(const float4*)(g_spec_p + s * SPL + rowb + d4 * 4);
                float4 vk = *(const float4*)(g_spec_p + s * SPL + rowb + 1024 + d4 * 4);
                q.x += vq.x; q.y += vq.y; q.z += vq.z; q.w += vq.w;
                kk.x += vk.x; kk.y += vk.y; kk.z += vk.z; kk.w += vk.w;
            }
            dot = fmaf(q.x, kk.x, dot); dot = fmaf(q.y, kk.y, dot);
            dot = fmaf(q.z, kk.z, dot); dot = fmaf(q.w, kk.w, dot);
        }

        float f = 1.f / (1.f + expf(-filt[h * 32 + k]));
        float stim = dot * 0.125f * f;

        const float a = d_a[0], bb = d_b[0];
        float scale = fmaxf(fabsf(stim), 1e-6f);
        float sn = stim / scale;
        float I = (fabsf(stim) > 0.5f) ? sn : sn * 0.1f;
        float v = 0.f, w = 0.f;
        const float dt = 0.2f;
#pragma unroll
        for (int s = 0; s < 5; s++) {
            float dv = v - v * v * v * (1.f / 3.f) - w + I;
            float dw = (v + a - bb * w) * 10.f;
            v = fminf(fmaxf(v + dt * dv, -3.f), 3.f);
            w = fminf(fmaxf(w + dt * dw, -3.f), 3.f);
        }
        float resp = v * scale;
        out_resp[b * 512 + h * 32 + k] = resp;

        // ws2 = resp * (sum_s v_p), written as bf16 hi/lo
        const size_t wsb = ((size_t)m * 1024 + h * 64) / 4;   // uint2 index
#pragma unroll
        for (int d4 = 0; d4 < 16; d4++) {
            float4 vv = make_float4(0.f, 0.f, 0.f, 0.f);
#pragma unroll
            for (int s = 0; s < SKS; s++) {
                float4 p = *(const float4*)(g_spec_p + s * SPL + rowb + 2048 + d4 * 4);
                vv.x += p.x; vv.y += p.y; vv.z += p.z; vv.w += p.w;
            }
            float wv[4] = { resp * vv.x, resp * vv.y, resp * vv.z, resp * vv.w };
            ((uint2*)g_wshi)[wsb + d4] = pack_hilo4(wv, false);
            ((uint2*)g_wslo)[wsb + d4] = pack_hilo4(wv, true);
        }
    } else {
        const int bh = blockIdx.x - 8;
        const int b = bh >> 4, h = bh & 15;
        const int tid = threadIdx.x;
        if (tid >= 32) return;
        const float* qm = g_qm + b * 1024 + h * 64;
        float acc = b1[tid];
#pragma unroll
        for (int dd = 0; dd < 64; dd++)
            acc = fmaf(qm[dd] * (1.0f / Tc), W1[tid * 64 + dd], acc);
        float h1 = acc / (1.f + expf(-acc));
        float pp = h1 * W2[tid];
#pragma unroll
        for (int off = 16; off; off >>= 1)
            pp += __shfl_down_sync(0xffffffffu, pp, off);
        if (tid == 0) {
            float xv = pp + b2[0];
            float sp = (xv > 20.f) ? xv : log1pf(expf(xv));
            out_pulse[bh] = 4.0f + sp;
        }
    }
}

// ---------------------------------------------------------------------------
// Reduce Z partials (SKZ) -> g_Z
// ---------------------------------------------------------------------------
__global__ void reduce_Z()
{
    int i = blockIdx.x * blockDim.x + threadIdx.x;
    if (i >= 32768) return;
    float4 a = make_float4(0.f, 0.f, 0.f, 0.f);
#pragma unroll
    for (int s = 0; s < SKZ; s++) {
        float4 v = ((const float4*)g_Zp)[(size_t)s * 32768 + i];
        a.x += v.x; a.y += v.y; a.z += v.z; a.w += v.w;
    }
    ((float4*)g_Z)[i] = a;
}

// ---------------------------------------------------------------------------
// K_out: out[b,t,:] = sum_k sb[b,t,k] * Z[b*32+k][:]
// ---------------------------------------------------------------------------
__global__ __launch_bounds__(256) void out_expand_kernel(
    const float* __restrict__ sb, float* __restrict__ out)
{
    const int b = blockIdx.x, tt0 = blockIdx.y * 64;
    const int tid = threadIdx.x;
    const int d0 = tid * 4;

    __shared__ __align__(16) float sbs[64][32];
    {
        int e = tid;
#pragma unroll
        for (int i = 0; i < 2; i++, e += 256) {
            int ttt = e >> 3, k4 = (e & 7) * 4;
            *(float4*)&sbs[ttt][k4] =
                *(const float4*)(sb + ((size_t)b * Tc + tt0 + ttt) * 32 + k4);
        }
    }

    float zr[32][4];
#pragma unroll
    for (int k = 0; k < 32; k++) {
        float4 z = *(const float4*)(g_Z + (size_t)(b * 32 + k) * 1024 + d0);
        zr[k][0] = z.x; zr[k][1] = z.y; zr[k][2] = z.z; zr[k][3] = z.w;
    }
    __syncthreads();

    float* ob = out + ((size_t)b * Tc + tt0) * Dc + d0;
    for (int t = 0; t < 64; t++) {
        float a0 = 0.f, a1 = 0.f, a2 = 0.f, a3 = 0.f;
#pragma unroll
        for (int k8 = 0; k8 < 8; k8++) {
            float4 sv = *(const float4*)&sbs[t][k8 * 4];
            float sk[4] = { sv.x, sv.y, sv.z, sv.w };
#pragma unroll
            for (int ki = 0; ki < 4; ki++) {
                a0 = fmaf(sk[ki], zr[k8 * 4 + ki][0], a0);
                a1 = fmaf(sk[ki], zr[k8 * 4 + ki][1], a1);
                a2 = fmaf(sk[ki], zr[k8 * 4 + ki][2], a2);
                a3 = fmaf(sk[ki], zr[k8 * 4 + ki][3], a3);
            }
        }
        *(float4*)(ob + (size_t)t * Dc) = make_float4(a0, a1, a2, a3);
    }
}

// ---------------------------------------------------------------------------
// Launch
// ---------------------------------------------------------------------------
extern "C" void kernel_launch(void* const* d_in, const int* in_sizes, int n_in,
                              void* d_out, int out_size)
{
    const float* x    = (const float*)d_in[0];
    const float* sb   = (const float*)d_in[1];
    const float* Wqkv = (const float*)d_in[2];
    const float* Wout = (const float*)d_in[3];
    const float* a    = (const float*)d_in[4];
    const float* b    = (const float*)d_in[5];
    const float* W1   = (const float*)d_in[6];
    const float* b1   = (const float*)d_in[7];
    const float* W2   = (const float*)d_in[8];
    const float* b2   = (const float*)d_in[9];
    const float* filt = (const float*)d_in[10];

    float* out       = (float*)d_out;
    float* out_pulse = out + (size_t)Bc * Tc * Dc;
    float* out_resp  = out_pulse + Bc * Hc;

    float *pspec_p, *pZp;
    cudaGetSymbolAddress((void**)&pspec_p, g_spec_p);
    cudaGetSymbolAddress((void**)&pZp, g_Zp);
    __nv_bfloat16 *pxshi, *pxslo, *pwqhi, *pwqlo, *pwohi, *pwolo, *pwshi, *pwslo;
    cudaGetSymbolAddress((void**)&pxshi, g_xshi);
    cudaGetSymbolAddress((void**)&pxslo, g_xslo);
    cudaGetSymbolAddress((void**)&pwqhi, g_wqhi);
    cudaGetSymbolAddress((void**)&pwqlo, g_wqlo);
    cudaGetSymbolAddress((void**)&pwohi, g_wohi);
    cudaGetSymbolAddress((void**)&pwolo, g_wolo);
    cudaGetSymbolAddress((void**)&pwshi, g_wshi);
    cudaGetSymbolAddress((void**)&pwslo, g_wslo);

    const int GEMM_SMEM = 2 * STAGE_B;   // 81920 B
    cudaFuncSetAttribute(gemm_mma_sk, cudaFuncAttributeMaxDynamicSharedMemorySize,
                         GEMM_SMEM);

    // 0) split weights to bf16 hi/lo (independent of everything else)
    split_w_kernel<<<(1024 * 1024 + 255) / 256, 256>>>(Wqkv, Wout);

    // 1) xs partials + fused reduce (-> bf16 hi/lo) + xm
    xs_part_kernel<<<dim3(Bc, NS1), 256>>>(x, sb);
    reduce_xs_xm<<<(32768 + 1024 + 255) / 256, 256>>>();

    // 2) qm GEMV
    qm_gemv_kernel<<<512, 256>>>(Wqkv);

    // 3) spec partials = xs @ Wqkv^T  [HMMA, split-K 16]
    gemm_mma_sk<<<dim3(24, 1, SKS), 256, GEMM_SMEM>>>(
        pxshi, pxslo, pwqhi, pwqlo, pspec_p, 3072, 1024 / SKS);

    // 4) soliton (sums partials inline) + ws2 split + pulse MLP
    soliton_pulse_kernel<<<8 + 64, 256>>>(a, b, filt, W1, b1, W2, b2,
                                          out_resp, out_pulse);

    // 5) Z partials = ws2 @ Wout^T  [HMMA, split-K 16]
    gemm_mma_sk<<<dim3(8, 1, SKZ), 256, GEMM_SMEM>>>(
        pwshi, pwslo, pwohi, pwolo, pZp, 1024, 1024 / SKZ);
    reduce_Z<<<(32768 + 255) / 256, 256>>>();

    // 6) out = sb @ Z (per batch)
    out_expand_kernel<<<dim3(Bc, Tc / 64), 256>>>(sb, out);
}

// round 10
// speedup vs baseline: 2.2448x; 2.2448x over previous
#include <cuda_runtime.h>
#include <math.h>
#include <stdint.h>

// Problem constants
#define Bc  4
#define Tc  4096
#define Dc  1024
#define Hc  16
#define HDc 64
#define Kc  32

#define NS1 32      // t-slices for xs build (128 t each)
#define SKS 16      // split-K for spec GEMM (slab 64)
#define SKZ 32      // split-K for Z GEMM   (slab 32)

// ---------------- scratch (static device arrays) ----------------
__device__ float g_xs_p[NS1 * 128 * 1024];       // xs partials (16.8 MB)
__device__ float g_xm_p[NS1 * Bc * 1024];        // xmean partials
__device__ float g_xs[128 * 1024];               // xs[b*32+k][d]
__device__ float g_xm[Bc * 1024];                // sum_t x
__device__ float g_qm[Bc * 1024];                // xm @ Wq^T (unnormalized)
__device__ float g_spec_p[SKS * 128 * 3072];     // spec GEMM partials (25 MB)
__device__ float g_ws2[128 * 1024];              // resp * v_spec
__device__ float g_Zp[SKZ * 128 * 1024];         // Z GEMM partials
__device__ float g_Z[128 * 1024];                // ws2 @ W_out^T

// ---------------------------------------------------------------------------
// K1: xs partials + xm partials.  grid (b=4, slice=32), 256 threads.
// Each slice covers 128 t's.
// ---------------------------------------------------------------------------
__global__ __launch_bounds__(256) void xs_part_kernel(
    const float* __restrict__ x, const float* __restrict__ sb)
{
    const int b = blockIdx.x, s = blockIdx.y;
    const int tid = threadIdx.x;
    const int d0 = tid * 4;
    const int t0 = s * 128;

    __shared__ __align__(16) float sbs[128][32];
    {
        int e = tid;
#pragma unroll
        for (int i = 0; i < 4; i++, e += 256) {
            int tt = e >> 3, k4 = (e & 7) * 4;
            *(float4*)&sbs[tt][k4] =
                *(const float4*)(sb + ((size_t)b * Tc + t0 + tt) * 32 + k4);
        }
    }
    __syncthreads();

    float acc[32][4];
#pragma unroll
    for (int k = 0; k < 32; k++)
#pragma unroll
        for (int j = 0; j < 4; j++) acc[k][j] = 0.f;
    float am[4] = {0.f, 0.f, 0.f, 0.f};

    const float* xb = x + ((size_t)b * Tc + t0) * Dc + d0;
    for (int t = 0; t < 128; t++) {
        float4 xv = *(const float4*)(xb + (size_t)t * Dc);
        float v[4] = { xv.x, xv.y, xv.z, xv.w };
#pragma unroll
        for (int j = 0; j < 4; j++) am[j] += v[j];
#pragma unroll
        for (int k8 = 0; k8 < 8; k8++) {
            float4 sv = *(const float4*)&sbs[t][k8 * 4];
            float sk[4] = { sv.x, sv.y, sv.z, sv.w };
#pragma unroll
            for (int ki = 0; ki < 4; ki++)
#pragma unroll
                for (int j = 0; j < 4; j++)
                    acc[k8 * 4 + ki][j] = fmaf(sk[ki], v[j], acc[k8 * 4 + ki][j]);
        }
    }

    float* op = g_xs_p + (size_t)s * 131072 + (size_t)b * 32 * 1024 + d0;
#pragma unroll
    for (int k = 0; k < 32; k++)
        *(float4*)(op + k * 1024) = make_float4(acc[k][0], acc[k][1],
                                                acc[k][2], acc[k][3]);
    *(float4*)(g_xm_p + (size_t)s * 4096 + b * 1024 + d0) =
        make_float4(am[0], am[1], am[2], am[3]);
}

// ---------------------------------------------------------------------------
// Reduce xs (32768 f4) and xm (1024 f4) partials over NS1 slices.
// ---------------------------------------------------------------------------
__global__ void reduce_xs_xm()
{
    int i = blockIdx.x * blockDim.x + threadIdx.x;
    if (i < 32768) {
        float4 a = make_float4(0.f, 0.f, 0.f, 0.f);
#pragma unroll 4
        for (int s = 0; s < NS1; s++) {
            float4 v = ((const float4*)g_xs_p)[(size_t)s * 32768 + i];
            a.x += v.x; a.y += v.y; a.z += v.z; a.w += v.w;
        }
        ((float4*)g_xs)[i] = a;
    } else if (i < 32768 + 1024) {
        int j = i - 32768;
        float4 a = make_float4(0.f, 0.f, 0.f, 0.f);
#pragma unroll 4
        for (int s = 0; s < NS1; s++) {
            float4 v = ((const float4*)g_xm_p)[(size_t)s * 1024 + j];
            a.x += v.x; a.y += v.y; a.z += v.z; a.w += v.w;
        }
        ((float4*)g_xm)[j] = a;
    }
}

// ---------------------------------------------------------------------------
// GEMM NT split-K (M=128 fixed) with register double-buffer + fused qm GEMV.
// Blocks [0, nGemm): Cp[z][m][n] = sum_{k in slab z} A[m,k]*Bm[n,k]
//   z = blockIdx.x / nCols, col0 = (blockIdx.x % nCols)*128.
// Blocks [nGemm, nGemm+512): qm GEMV g_qm[b*1024+o] = xm[b,:].Bm[o,:]
//   (only launched with extra blocks for the spec GEMM, Bm = Wqkv).
// ---------------------------------------------------------------------------
__global__ __launch_bounds__(256) void gemm_qm_kernel(
    const float* __restrict__ A, const float* __restrict__ Bm,
    float* __restrict__ Cp, int N, int kPerSplit, int nGemm)
{
    const int tid = threadIdx.x;
    if ((int)blockIdx.x >= nGemm) {
        // ---- qm GEMV branch (8 warps per block) ----
        const int w = (blockIdx.x - nGemm) * 8 + (tid >> 5);   // 0..4095
        const int lane = tid & 31;
        const int b = w >> 10, o = w & 1023;
        const float4* xm = (const float4*)(g_xm + b * 1024);
        const float4* wr = (const float4*)(Bm + (size_t)o * 1024);
        float s = 0.f;
#pragma unroll
        for (int j = 0; j < 8; j++) {
            float4 a = xm[lane + j * 32];
            float4 c = wr[lane + j * 32];
            s = fmaf(a.x, c.x, s); s = fmaf(a.y, c.y, s);
            s = fmaf(a.z, c.z, s); s = fmaf(a.w, c.w, s);
        }
#pragma unroll
        for (int off = 16; off; off >>= 1)
            s += __shfl_down_sync(0xffffffffu, s, off);
        if (lane == 0) g_qm[b * 1024 + o] = s;
        return;
    }

    // ---- GEMM branch ----
    __shared__ float As[2][8][128];
    __shared__ float Bs[2][8][128];
    const int nCols = N >> 7;
    const int col0 = (blockIdx.x % nCols) * 128;
    const int z = blockIdx.x / nCols;
    const int kb = z * kPerSplit;
    const int lrow = tid >> 1, lk = (tid & 1) * 4;
    const int ty = tid >> 4, tx = tid & 15;

    float acc[8][8];
#pragma unroll
    for (int i = 0; i < 8; i++)
#pragma unroll
        for (int j = 0; j < 8; j++) acc[i][j] = 0.f;

    const float* Ap = A + (size_t)lrow * 1024 + lk;
    const float* Bp = Bm + (size_t)(col0 + lrow) * 1024 + lk;

    float4 av = *(const float4*)(Ap + kb);
    float4 bv = *(const float4*)(Bp + kb);
    As[0][lk + 0][lrow] = av.x; As[0][lk + 1][lrow] = av.y;
    As[0][lk + 2][lrow] = av.z; As[0][lk + 3][lrow] = av.w;
    Bs[0][lk + 0][lrow] = bv.x; Bs[0][lk + 1][lrow] = bv.y;
    Bs[0][lk + 2][lrow] = bv.z; Bs[0][lk + 3][lrow] = bv.w;
    __syncthreads();

    const int nT = kPerSplit >> 3;
    for (int kt = 0; kt < nT; kt++) {
        const int buf = kt & 1;
        if (kt + 1 < nT) {                  // prefetch next tile (LDG early)
            av = *(const float4*)(Ap + kb + (kt + 1) * 8);
            bv = *(const float4*)(Bp + kb + (kt + 1) * 8);
        }
#pragma unroll
        for (int kk = 0; kk < 8; kk++) {
            float ra[8], rb[8];
#pragma unroll
            for (int i = 0; i < 8; i++) ra[i] = As[buf][kk][ty * 8 + i];
#pragma unroll
            for (int j = 0; j < 8; j++) rb[j] = Bs[buf][kk][tx * 8 + j];
#pragma unroll
            for (int i = 0; i < 8; i++)
#pragma unroll
                for (int j = 0; j < 8; j++)
                    acc[i][j] = fmaf(ra[i], rb[j], acc[i][j]);
        }
        if (kt + 1 < nT) {                  // store into other buffer
            const int nb = buf ^ 1;
            As[nb][lk + 0][lrow] = av.x; As[nb][lk + 1][lrow] = av.y;
            As[nb][lk + 2][lrow] = av.z; As[nb][lk + 3][lrow] = av.w;
            Bs[nb][lk + 0][lrow] = bv.x; Bs[nb][lk + 1][lrow] = bv.y;
            Bs[nb][lk + 2][lrow] = bv.z; Bs[nb][lk + 3][lrow] = bv.w;
        }
        __syncthreads();
    }

    float* C = Cp + (size_t)z * 128 * N;
#pragma unroll
    for (int i = 0; i < 8; i++) {
        float* Cr = C + (size_t)(ty * 8 + i) * N + col0 + tx * 8;
#pragma unroll
        for (int j = 0; j < 8; j += 4)
            *(float4*)(Cr + j) = make_float4(acc[i][j], acc[i][j + 1],
                                             acc[i][j + 2], acc[i][j + 3]);
    }
}

// ---------------------------------------------------------------------------
// Fused: blocks 0..127 (one per m): reduce spec partials (16 slabs) for the
// whole 3072-row, then 16 ODEs (one per h), response, ws2 = resp * v.
// Blocks 128..191: pulse-width MLP per (b,h).
// ---------------------------------------------------------------------------
__global__ __launch_bounds__(256) void soliton_pulse_kernel(
    const float* __restrict__ d_a, const float* __restrict__ d_b,
    const float* __restrict__ filt,
    const float* __restrict__ W1, const float* __restrict__ b1,
    const float* __restrict__ W2, const float* __restrict__ b2,
    float* __restrict__ out_resp, float* __restrict__ out_pulse)
{
    const int tid = threadIdx.x;
    if (blockIdx.x < 128) {
        const int m = blockIdx.x;
        const int b = m >> 5, k = m & 31;
        __shared__ __align__(16) float srow[3072];
        __shared__ float resp_s[16];

        // reduce 16 slabs for this m-row (768 float4, 3 per thread)
        const size_t SPL4 = 128 * 3072 / 4;
        const size_t rb4 = (size_t)m * 768;
#pragma unroll
        for (int j = 0; j < 3; j++) {
            int idx = tid + j * 256;
            float4 a = make_float4(0.f, 0.f, 0.f, 0.f);
#pragma unroll
            for (int s = 0; s < SKS; s++) {
                float4 v = ((const float4*)g_spec_p)[s * SPL4 + rb4 + idx];
                a.x += v.x; a.y += v.y; a.z += v.z; a.w += v.w;
            }
            ((float4*)srow)[idx] = a;
        }
        __syncthreads();

        if (tid < 16) {
            const int h = tid;
            float dot = 0.f;
#pragma unroll
            for (int d = 0; d < 64; d++)
                dot = fmaf(srow[h * 64 + d], srow[1024 + h * 64 + d], dot);

            float f = 1.f / (1.f + expf(-filt[h * 32 + k]));
            float stim = dot * 0.125f * f;

            const float a = d_a[0], bb = d_b[0];
            float scale = fmaxf(fabsf(stim), 1e-6f);
            float sn = stim / scale;
            float I = (fabsf(stim) > 0.5f) ? sn : sn * 0.1f;
            float v = 0.f, w = 0.f;
            const float dt = 0.2f;
#pragma unroll
            for (int s = 0; s < 5; s++) {
                float dv = v - v * v * v * (1.f / 3.f) - w + I;
                float dw = (v + a - bb * w) * 10.f;
                v = fminf(fmaxf(v + dt * dv, -3.f), 3.f);
                w = fminf(fmaxf(w + dt * dw, -3.f), 3.f);
            }
            float resp = v * scale;
            resp_s[h] = resp;
            out_resp[b * 512 + h * 32 + k] = resp;
        }
        __syncthreads();

        // ws2 = resp[h] * v_spec  (256 float4 = 1024 floats)
        {
            const int h = tid >> 4;
            float r = resp_s[h];
            float4 vv = ((const float4*)srow)[512 + tid];
            ((float4*)g_ws2)[(size_t)m * 256 + tid] =
                make_float4(r * vv.x, r * vv.y, r * vv.z, r * vv.w);
        }
    } else {
        const int bh = blockIdx.x - 128;
        const int b = bh >> 4, h = bh & 15;
        if (tid >= 32) return;
        const float* qm = g_qm + b * 1024 + h * 64;
        float acc = b1[tid];
#pragma unroll
        for (int dd = 0; dd < 64; dd++)
            acc = fmaf(qm[dd] * (1.0f / Tc), W1[tid * 64 + dd], acc);
        float h1 = acc / (1.f + expf(-acc));          // silu
        float pp = h1 * W2[tid];
#pragma unroll
        for (int off = 16; off; off >>= 1)
            pp += __shfl_down_sync(0xffffffffu, pp, off);
        if (tid == 0) {
            float xv = pp + b2[0];
            float sp = (xv > 20.f) ? xv : log1pf(expf(xv));  // softplus
            out_pulse[bh] = 4.0f + sp;
        }
    }
}

// ---------------------------------------------------------------------------
// Reduce Z partials (SKZ) -> g_Z
// ---------------------------------------------------------------------------
__global__ void reduce_Z()
{
    int i = blockIdx.x * blockDim.x + threadIdx.x;
    if (i >= 32768) return;
    float4 a = make_float4(0.f, 0.f, 0.f, 0.f);
#pragma unroll 8
    for (int s = 0; s < SKZ; s++) {
        float4 v = ((const float4*)g_Zp)[(size_t)s * 32768 + i];
        a.x += v.x; a.y += v.y; a.z += v.z; a.w += v.w;
    }
    ((float4*)g_Z)[i] = a;
}

// ---------------------------------------------------------------------------
// K_out: out[b,t,:] = sum_k sb[b,t,k] * Z[b*32+k][:]
// ---------------------------------------------------------------------------
__global__ __launch_bounds__(256) void out_expand_kernel(
    const float* __restrict__ sb, float* __restrict__ out)
{
    const int b = blockIdx.x, tt0 = blockIdx.y * 64;
    const int tid = threadIdx.x;
    const int d0 = tid * 4;

    __shared__ __align__(16) float sbs[64][32];
    {
        int e = tid;
#pragma unroll
        for (int i = 0; i < 2; i++, e += 256) {
            int ttt = e >> 3, k4 = (e & 7) * 4;
            *(float4*)&sbs[ttt][k4] =
                *(const float4*)(sb + ((size_t)b * Tc + tt0 + ttt) * 32 + k4);
        }
    }

    float zr[32][4];
#pragma unroll
    for (int k = 0; k < 32; k++) {
        float4 z = *(const float4*)(g_Z + (size_t)(b * 32 + k) * 1024 + d0);
        zr[k][0] = z.x; zr[k][1] = z.y; zr[k][2] = z.z; zr[k][3] = z.w;
    }
    __syncthreads();

    float* ob = out + ((size_t)b * Tc + tt0) * Dc + d0;
    for (int t = 0; t < 64; t++) {
        float a0 = 0.f, a1 = 0.f, a2 = 0.f, a3 = 0.f;
#pragma unroll
        for (int k8 = 0; k8 < 8; k8++) {
            float4 sv = *(const float4*)&sbs[t][k8 * 4];
            float sk[4] = { sv.x, sv.y, sv.z, sv.w };
#pragma unroll
            for (int ki = 0; ki < 4; ki++) {
                a0 = fmaf(sk[ki], zr[k8 * 4 + ki][0], a0);
                a1 = fmaf(sk[ki], zr[k8 * 4 + ki][1], a1);
                a2 = fmaf(sk[ki], zr[k8 * 4 + ki][2], a2);
                a3 = fmaf(sk[ki], zr[k8 * 4 + ki][3], a3);
            }
        }
        *(float4*)(ob + (size_t)t * Dc) = make_float4(a0, a1, a2, a3);
    }
}

// ---------------------------------------------------------------------------
// Launch
// Inputs: x, spectral_basis, W_qkv, W_out, a, b, W1, b1, W2, b2, spectral_filter
// Outputs: out (B*T*D) ++ pulse_widths (B*H) ++ response (B*H*K)
// ---------------------------------------------------------------------------
extern "C" void kernel_launch(void* const* d_in, const int* in_sizes, int n_in,
                              void* d_out, int out_size)
{
    const float* x    = (const float*)d_in[0];
    const float* sb   = (const float*)d_in[1];
    const float* Wqkv = (const float*)d_in[2];
    const float* Wout = (const float*)d_in[3];
    const float* a    = (const float*)d_in[4];
    const float* b    = (const float*)d_in[5];
    const float* W1   = (const float*)d_in[6];
    const float* b1   = (const float*)d_in[7];
    const float* W2   = (const float*)d_in[8];
    const float* b2   = (const float*)d_in[9];
    const float* filt = (const float*)d_in[10];

    float* out       = (float*)d_out;
    float* out_pulse = out + (size_t)Bc * Tc * Dc;
    float* out_resp  = out_pulse + Bc * Hc;

    float *pxs, *pspec_p, *pws2, *pZp;
    cudaGetSymbolAddress((void**)&pxs, g_xs);
    cudaGetSymbolAddress((void**)&pspec_p, g_spec_p);
    cudaGetSymbolAddress((void**)&pws2, g_ws2);
    cudaGetSymbolAddress((void**)&pZp, g_Zp);

    // 1) xs partials + reduce (+ xm)
    xs_part_kernel<<<dim3(Bc, NS1), 256>>>(x, sb);
    reduce_xs_xm<<<(32768 + 1024 + 255) / 256, 256>>>();

    // 2) spec partials = xs @ Wqkv^T  [split-K 16]  ++ qm GEMV (fused blocks)
    gemm_qm_kernel<<<24 * SKS + 512, 256>>>(pxs, Wqkv, pspec_p, 3072,
                                            1024 / SKS, 24 * SKS);

    // 3) spec reduce + soliton + ws2 + pulse MLP (fused)
    soliton_pulse_kernel<<<128 + 64, 256>>>(a, b, filt, W1, b1, W2, b2,
                                            out_resp, out_pulse);

    // 4) Z partials = ws2 @ Wout^T  [split-K 32] + reduce
    gemm_qm_kernel<<<8 * SKZ, 256>>>(pws2, Wout, pZp, 1024, 1024 / SKZ, 8 * SKZ);
    reduce_Z<<<(32768 + 255) / 256, 256>>>();

    // 5) out = sb @ Z (per batch)
    out_expand_kernel<<<dim3(Bc, Tc / 64), 256>>>(sb, out);
}

// round 11
// speedup vs baseline: 2.5617x; 1.1412x over previous
#include <cuda_runtime.h>
#include <cuda_bf16.h>
#include <math.h>
#include <stdint.h>

// Problem constants
#define Bc  4
#define Tc  4096
#define Dc  1024
#define Hc  16
#define HDc 64
#define Kc  32

#define NS1 32      // t-slices for xs build (128 t each)
#define SKS 8       // split-K for spec GEMM (slab 128)
#define SKZ 16      // split-K for Z GEMM   (slab 64)

// ---------------- scratch (static device arrays) ----------------
__device__ float g_xs_p[NS1 * 128 * 1024];       // xs partials
__device__ float g_xm_p[NS1 * Bc * 1024];        // xmean partials
__device__ float g_xm[Bc * 1024];                // sum_t x
__device__ float g_qm[Bc * 1024];                // xm @ Wq^T (unnormalized)
__device__ float g_spec_p[SKS * 128 * 3072];     // spec GEMM partials
__device__ float g_Zp[SKZ * 128 * 1024];         // Z GEMM partials
__device__ __nv_bfloat16 g_xshi[128 * 1024], g_xslo[128 * 1024];
__device__ __nv_bfloat16 g_wqhi[3 * 1024 * 1024], g_wqlo[3 * 1024 * 1024];
__device__ __nv_bfloat16 g_wohi[1024 * 1024], g_wolo[1024 * 1024];
__device__ __nv_bfloat16 g_wshi[128 * 1024], g_wslo[128 * 1024];
__device__ __nv_bfloat16 g_sbhi[Bc * Tc * 32], g_sblo[Bc * Tc * 32];
__device__ __nv_bfloat16 g_Zthi[Bc * 1024 * 32], g_Ztlo[Bc * 1024 * 32];

__device__ __forceinline__ uint32_t smem_u32(const void* p) {
    uint32_t a;
    asm("{ .reg .u64 t; cvta.to.shared.u64 t, %1; cvt.u32.u64 %0, t; }"
        : "=r"(a) : "l"(p));
    return a;
}
__device__ __forceinline__ uint2 pack_hilo4(const float* v, bool lo) {
    __nv_bfloat16 h[4];
#pragma unroll
    for (int j = 0; j < 4; j++) {
        __nv_bfloat16 hh = __float2bfloat16_rn(v[j]);
        h[j] = lo ? __float2bfloat16_rn(v[j] - __bfloat162float(hh)) : hh;
    }
    uint2 r;
    r.x = (uint32_t)__bfloat16_as_ushort(h[0]) |
          ((uint32_t)__bfloat16_as_ushort(h[1]) << 16);
    r.y = (uint32_t)__bfloat16_as_ushort(h[2]) |
          ((uint32_t)__bfloat16_as_ushort(h[3]) << 16);
    return r;
}

#define MMA_OP(d, A, b0, b1)                                                  \
    asm volatile("mma.sync.aligned.m16n8k16.row.col.f32.bf16.bf16.f32 "       \
                 "{%0,%1,%2,%3},{%4,%5,%6,%7},{%8,%9},{%0,%1,%2,%3};"         \
                 : "+f"(d[0]), "+f"(d[1]), "+f"(d[2]), "+f"(d[3])             \
                 : "r"(A[0]), "r"(A[1]), "r"(A[2]), "r"(A[3]),                \
                   "r"(b0), "r"(b1))

// ---------------------------------------------------------------------------
// Split Wqkv (3M) and Wout (1M) into bf16 hi/lo.
// ---------------------------------------------------------------------------
__global__ void split_w_kernel(const float* __restrict__ Wqkv,
                               const float* __restrict__ Wout)
{
    int i = blockIdx.x * blockDim.x + threadIdx.x;
    const int NQ4 = 3 * 1024 * 1024 / 4;
    const float* src;
    __nv_bfloat16 *hi, *lo;
    int j;
    if (i < NQ4) { src = Wqkv; hi = g_wqhi; lo = g_wqlo; j = i; }
    else { src = Wout; hi = g_wohi; lo = g_wolo; j = i - NQ4;
           if (j >= 1024 * 1024 / 4) return; }
    float4 v = ((const float4*)src)[j];
    float vv[4] = { v.x, v.y, v.z, v.w };
    ((uint2*)hi)[j] = pack_hilo4(vv, false);
    ((uint2*)lo)[j] = pack_hilo4(vv, true);
}

// ---------------------------------------------------------------------------
// K1: xs partials + xm partials + sb bf16 hi/lo split (fused).
// ---------------------------------------------------------------------------
__global__ __launch_bounds__(256) void xs_part_kernel(
    const float* __restrict__ x, const float* __restrict__ sb)
{
    const int b = blockIdx.x, s = blockIdx.y;
    const int tid = threadIdx.x;
    const int d0 = tid * 4;
    const int t0 = s * 128;

    __shared__ __align__(16) float sbs[128][32];
    {
        int e = tid;
#pragma unroll
        for (int i = 0; i < 4; i++, e += 256) {
            int tt = e >> 3, k4 = (e & 7) * 4;
            size_t gofs = ((size_t)b * Tc + t0 + tt) * 32 + k4;
            float4 v = *(const float4*)(sb + gofs);
            *(float4*)&sbs[tt][k4] = v;
            float vv[4] = { v.x, v.y, v.z, v.w };
            ((uint2*)g_sbhi)[gofs / 4] = pack_hilo4(vv, false);
            ((uint2*)g_sblo)[gofs / 4] = pack_hilo4(vv, true);
        }
    }
    __syncthreads();

    float acc[32][4];
#pragma unroll
    for (int k = 0; k < 32; k++)
#pragma unroll
        for (int j = 0; j < 4; j++) acc[k][j] = 0.f;
    float am[4] = {0.f, 0.f, 0.f, 0.f};

    const float* xb = x + ((size_t)b * Tc + t0) * Dc + d0;
    for (int t = 0; t < 128; t++) {
        float4 xv = *(const float4*)(xb + (size_t)t * Dc);
        float v[4] = { xv.x, xv.y, xv.z, xv.w };
#pragma unroll
        for (int j = 0; j < 4; j++) am[j] += v[j];
#pragma unroll
        for (int k8 = 0; k8 < 8; k8++) {
            float4 sv = *(const float4*)&sbs[t][k8 * 4];
            float sk[4] = { sv.x, sv.y, sv.z, sv.w };
#pragma unroll
            for (int ki = 0; ki < 4; ki++)
#pragma unroll
                for (int j = 0; j < 4; j++)
                    acc[k8 * 4 + ki][j] = fmaf(sk[ki], v[j], acc[k8 * 4 + ki][j]);
        }
    }

    float* op = g_xs_p + (size_t)s * 131072 + (size_t)b * 32 * 1024 + d0;
#pragma unroll
    for (int k = 0; k < 32; k++)
        *(float4*)(op + k * 1024) = make_float4(acc[k][0], acc[k][1],
                                                acc[k][2], acc[k][3]);
    *(float4*)(g_xm_p + (size_t)s * 4096 + b * 1024 + d0) =
        make_float4(am[0], am[1], am[2], am[3]);
}

// ---------------------------------------------------------------------------
// Reduce xs partials -> bf16 hi/lo; xm partials -> fp32.
// ---------------------------------------------------------------------------
__global__ void reduce_xs_xm()
{
    int i = blockIdx.x * blockDim.x + threadIdx.x;
    if (i < 32768) {
        float4 a = make_float4(0.f, 0.f, 0.f, 0.f);
#pragma unroll 4
        for (int s = 0; s < NS1; s++) {
            float4 v = ((const float4*)g_xs_p)[(size_t)s * 32768 + i];
            a.x += v.x; a.y += v.y; a.z += v.z; a.w += v.w;
        }
        float vv[4] = { a.x, a.y, a.z, a.w };
        ((uint2*)g_xshi)[i] = pack_hilo4(vv, false);
        ((uint2*)g_xslo)[i] = pack_hilo4(vv, true);
    } else if (i < 32768 + 1024) {
        int j = i - 32768;
        float4 a = make_float4(0.f, 0.f, 0.f, 0.f);
#pragma unroll 4
        for (int s = 0; s < NS1; s++) {
            float4 v = ((const float4*)g_xm_p)[(size_t)s * 1024 + j];
            a.x += v.x; a.y += v.y; a.z += v.z; a.w += v.w;
        }
        ((float4*)g_xm)[j] = a;
    }
}

// ---------------------------------------------------------------------------
// HMMA GEMM NT, M=128, split-K, 3-product bf16 split + fused qm GEMV blocks.
// ---------------------------------------------------------------------------
#define KT      32
#define RB      80
#define TILE_B  (128 * RB)
#define STAGE_B (4 * TILE_B)

__global__ void __launch_bounds__(256) gemm_mma_sk(
    const __nv_bfloat16* __restrict__ Ahi, const __nv_bfloat16* __restrict__ Alo,
    const __nv_bfloat16* __restrict__ Bhi, const __nv_bfloat16* __restrict__ Blo,
    float* __restrict__ Cp, int N, int kPerSplit, int nGemm,
    const float* __restrict__ WqF)
{
    const int tid = threadIdx.x;
    if ((int)blockIdx.x >= nGemm) {
        const int w = (blockIdx.x - nGemm) * 8 + (tid >> 5);
        const int lane = tid & 31;
        const int b = w >> 10, o = w & 1023;
        const float4* xm = (const float4*)(g_xm + b * 1024);
        const float4* wr = (const float4*)(WqF + (size_t)o * 1024);
        float s = 0.f;
#pragma unroll
        for (int j = 0; j < 8; j++) {
            float4 a = xm[lane + j * 32];
            float4 c = wr[lane + j * 32];
            s = fmaf(a.x, c.x, s); s = fmaf(a.y, c.y, s);
            s = fmaf(a.z, c.z, s); s = fmaf(a.w, c.w, s);
        }
#pragma unroll
        for (int off = 16; off; off >>= 1)
            s += __shfl_down_sync(0xffffffffu, s, off);
        if (lane == 0) g_qm[b * 1024 + o] = s;
        return;
    }

    extern __shared__ char smem[];
    const int Kd = 1024;
    const uint32_t sbase = smem_u32(smem);
    const int wid = tid >> 5, lane = tid & 31;
    const int nCols = N >> 7;
    const int col0 = (blockIdx.x % nCols) * 128;
    const int kb = (blockIdx.x / nCols) * kPerSplit;
    const int wm = wid >> 2, wn = wid & 3;

    const __nv_bfloat16* s0 = Ahi + kb;
    const __nv_bfloat16* s1 = Alo + kb;
    const __nv_bfloat16* s2 = Bhi + (size_t)col0 * Kd + kb;
    const __nv_bfloat16* s3 = Blo + (size_t)col0 * Kd + kb;

    const int e0 = tid, e1 = tid + 256;
    const int r0c = e0 >> 2, c0c = e0 & 3;
    const int r1c = e1 >> 2, c1c = e1 & 3;

#define LOAD_STAGE(kt, buf)                                                   \
    do {                                                                      \
        uint32_t db = sbase + (buf) * STAGE_B;                                \
        const __nv_bfloat16* srcs[4] = { s0, s1, s2, s3 };                    \
        _Pragma("unroll")                                                     \
        for (int a = 0; a < 4; a++) {                                         \
            const char* g0 = (const char*)(srcs[a] + (size_t)r0c * Kd + (kt) * KT) + c0c * 16; \
            const char* g1 = (const char*)(srcs[a] + (size_t)r1c * Kd + (kt) * KT) + c1c * 16; \
            uint32_t p0 = db + a * TILE_B + r0c * RB + c0c * 16;              \
            uint32_t p1 = db + a * TILE_B + r1c * RB + c1c * 16;              \
            asm volatile("cp.async.cg.shared.global [%0],[%1],16;" :: "r"(p0), "l"(g0)); \
            asm volatile("cp.async.cg.shared.global [%0],[%1],16;" :: "r"(p1), "l"(g1)); \
        }                                                                     \
        asm volatile("cp.async.commit_group;");                               \
    } while (0)

    float acc[4][4][4];
#pragma unroll
    for (int i = 0; i < 4; i++)
#pragma unroll
        for (int j = 0; j < 4; j++)
#pragma unroll
            for (int q = 0; q < 4; q++) acc[i][j][q] = 0.f;

    LOAD_STAGE(0, 0);
    int buf = 0;
    const int nTiles = kPerSplit / KT;

    for (int kt = 0; kt < nTiles; kt++) {
        asm volatile("cp.async.wait_group 0;");
        __syncthreads();
        if (kt + 1 < nTiles) LOAD_STAGE(kt + 1, buf ^ 1);

        const uint32_t db = sbase + buf * STAGE_B;
#pragma unroll
        for (int ks = 0; ks < 2; ks++) {
            uint32_t rah[4][4], ral[4][4];
#pragma unroll
            for (int mf = 0; mf < 4; mf++) {
                int r = wm * 64 + mf * 16 + (lane & 15);
                uint32_t ad = db + r * RB + ks * 32 + ((lane >> 4) & 1) * 16;
                asm volatile("ldmatrix.sync.aligned.m8n8.x4.shared.b16 {%0,%1,%2,%3},[%4];"
                    : "=r"(rah[mf][0]), "=r"(rah[mf][1]), "=r"(rah[mf][2]), "=r"(rah[mf][3])
                    : "r"(ad));
                asm volatile("ldmatrix.sync.aligned.m8n8.x4.shared.b16 {%0,%1,%2,%3},[%4];"
                    : "=r"(ral[mf][0]), "=r"(ral[mf][1]), "=r"(ral[mf][2]), "=r"(ral[mf][3])
                    : "r"(ad + TILE_B));
            }
            uint32_t rbh[2][4], rbl[2][4];
#pragma unroll
            for (int np = 0; np < 2; np++) {
                int r = wn * 32 + (np * 2 + (lane >> 4)) * 8 + (lane & 7);
                uint32_t bd = db + 2 * TILE_B + r * RB + ks * 32 + ((lane >> 3) & 1) * 16;
                asm volatile("ldmatrix.sync.aligned.m8n8.x4.shared.b16 {%0,%1,%2,%3},[%4];"
                    : "=r"(rbh[np][0]), "=r"(rbh[np][1]), "=r"(rbh[np][2]), "=r"(rbh[np][3])
                    : "r"(bd));
                asm volatile("ldmatrix.sync.aligned.m8n8.x4.shared.b16 {%0,%1,%2,%3},[%4];"
                    : "=r"(rbl[np][0]), "=r"(rbl[np][1]), "=r"(rbl[np][2]), "=r"(rbl[np][3])
                    : "r"(bd + TILE_B));
            }
#pragma unroll
            for (int mf = 0; mf < 4; mf++)
#pragma unroll
                for (int nf = 0; nf < 4; nf++)
                    MMA_OP(acc[mf][nf], rah[mf], rbh[nf >> 1][(nf & 1) * 2],
                           rbh[nf >> 1][(nf & 1) * 2 + 1]);
#pragma unroll
            for (int mf = 0; mf < 4; mf++)
#pragma unroll
                for (int nf = 0; nf < 4; nf++)
                    MMA_OP(acc[mf][nf], rah[mf], rbl[nf >> 1][(nf & 1) * 2],
                           rbl[nf >> 1][(nf & 1) * 2 + 1]);
#pragma unroll
            for (int mf = 0; mf < 4; mf++)
#pragma unroll
                for (int nf = 0; nf < 4; nf++)
                    MMA_OP(acc[mf][nf], ral[mf], rbh[nf >> 1][(nf & 1) * 2],
                           rbh[nf >> 1][(nf & 1) * 2 + 1]);
        }
        __syncthreads();
        buf ^= 1;
    }

    float* C = Cp + (size_t)(blockIdx.x / nCols) * 128 * N;
    const int mrow = lane >> 2, ncol = (lane & 3) * 2;
#pragma unroll
    for (int mf = 0; mf < 4; mf++) {
#pragma unroll
        for (int nf = 0; nf < 4; nf++) {
            int r  = wm * 64 + mf * 16 + mrow;
            int cc = col0 + wn * 32 + nf * 8 + ncol;
            *(float2*)(C + (size_t)r * N + cc) =
                make_float2(acc[mf][nf][0], acc[mf][nf][1]);
            *(float2*)(C + (size_t)(r + 8) * N + cc) =
                make_float2(acc[mf][nf][2], acc[mf][nf][3]);
        }
    }
#undef LOAD_STAGE
}

// ---------------------------------------------------------------------------
// Fused: blocks 0..127: reduce spec partials + 16 ODEs + ws2 bf16 split.
// Blocks 128..191: pulse MLP.
// ---------------------------------------------------------------------------
__global__ __launch_bounds__(256) void soliton_pulse_kernel(
    const float* __restrict__ d_a, const float* __restrict__ d_b,
    const float* __restrict__ filt,
    const float* __restrict__ W1, const float* __restrict__ b1,
    const float* __restrict__ W2, const float* __restrict__ b2,
    float* __restrict__ out_resp, float* __restrict__ out_pulse)
{
    const int tid = threadIdx.x;
    if (blockIdx.x < 128) {
        const int m = blockIdx.x;
        const int b = m >> 5, k = m & 31;
        __shared__ __align__(16) float srow[3072];
        __shared__ float resp_s[16];

        const size_t SPL4 = 128 * 3072 / 4;
        const size_t rb4 = (size_t)m * 768;
#pragma unroll
        for (int j = 0; j < 3; j++) {
            int idx = tid + j * 256;
            float4 a = make_float4(0.f, 0.f, 0.f, 0.f);
#pragma unroll
            for (int s = 0; s < SKS; s++) {
                float4 v = ((const float4*)g_spec_p)[s * SPL4 + rb4 + idx];
                a.x += v.x; a.y += v.y; a.z += v.z; a.w += v.w;
            }
            ((float4*)srow)[idx] = a;
        }
        __syncthreads();

        if (tid < 16) {
            const int h = tid;
            float dot = 0.f;
#pragma unroll
            for (int d = 0; d < 64; d++)
                dot = fmaf(srow[h * 64 + d], srow[1024 + h * 64 + d], dot);

            float f = 1.f / (1.f + expf(-filt[h * 32 + k]));
            float stim = dot * 0.125f * f;

            const float a = d_a[0], bb = d_b[0];
            float scale = fmaxf(fabsf(stim), 1e-6f);
            float sn = stim / scale;
            float I = (fabsf(stim) > 0.5f) ? sn : sn * 0.1f;
            float v = 0.f, w = 0.f;
            const float dt = 0.2f;
#pragma unroll
            for (int s = 0; s < 5; s++) {
                float dv = v - v * v * v * (1.f / 3.f) - w + I;
                float dw = (v + a - bb * w) * 10.f;
                v = fminf(fmaxf(v + dt * dv, -3.f), 3.f);
                w = fminf(fmaxf(w + dt * dw, -3.f), 3.f);
            }
            float resp = v * scale;
            resp_s[h] = resp;
            out_resp[b * 512 + h * 32 + k] = resp;
        }
        __syncthreads();

        {
            const int h = tid >> 4;
            float r = resp_s[h];
            float4 vv = ((const float4*)srow)[512 + tid];
            float wv[4] = { r * vv.x, r * vv.y, r * vv.z, r * vv.w };
            ((uint2*)g_wshi)[(size_t)m * 256 + tid] = pack_hilo4(wv, false);
            ((uint2*)g_wslo)[(size_t)m * 256 + tid] = pack_hilo4(wv, true);
        }
    } else {
        const int bh = blockIdx.x - 128;
        const int b = bh >> 4, h = bh & 15;
        if (tid >= 32) return;
        const float* qm = g_qm + b * 1024 + h * 64;
        float acc = b1[tid];
#pragma unroll
        for (int dd = 0; dd < 64; dd++)
            acc = fmaf(qm[dd] * (1.0f / Tc), W1[tid * 64 + dd], acc);
        float h1 = acc / (1.f + expf(-acc));
        float pp = h1 * W2[tid];
#pragma unroll
        for (int off = 16; off; off >>= 1)
            pp += __shfl_down_sync(0xffffffffu, pp, off);
        if (tid == 0) {
            float xv = pp + b2[0];
            float sp = (xv > 20.f) ? xv : log1pf(expf(xv));
            out_pulse[bh] = 4.0f + sp;
        }
    }
}

// ---------------------------------------------------------------------------
// Reduce Z partials -> Zt (transposed, bf16 hi/lo): Zt[b][d][k] = Z[b*32+k][d]
// ---------------------------------------------------------------------------
__global__ void reduce_Zt()
{
    int i = blockIdx.x * blockDim.x + threadIdx.x;
    if (i >= 32768) return;
    const int m = i >> 8, d0 = (i & 255) * 4;
    const int b = m >> 5, k = m & 31;
    float4 a = make_float4(0.f, 0.f, 0.f, 0.f);
#pragma unroll
    for (int s = 0; s < SKZ; s++) {
        float4 v = ((const float4*)g_Zp)[(size_t)s * 32768 + i];
        a.x += v.x; a.y += v.y; a.z += v.z; a.w += v.w;
    }
    float vv[4] = { a.x, a.y, a.z, a.w };
#pragma unroll
    for (int j = 0; j < 4; j++) {
        __nv_bfloat16 hh = __float2bfloat16_rn(vv[j]);
        __nv_bfloat16 ll = __float2bfloat16_rn(vv[j] - __bfloat162float(hh));
        size_t oi = ((size_t)b * 1024 + d0 + j) * 32 + k;
        g_Zthi[oi] = hh;
        g_Ztlo[oi] = ll;
    }
}

// ---------------------------------------------------------------------------
// out HMMA: out[b, t0:t0+128, d0:d0+128] = sb[b,t,:] @ Zt[b,d,:]^T  (K=32)
// ---------------------------------------------------------------------------
__global__ __launch_bounds__(256) void out_mma_kernel(float* __restrict__ out)
{
    __shared__ __align__(16) char smem[4 * TILE_B];
    const int tid = threadIdx.x, wid = tid >> 5, lane = tid & 31;
    const int t0 = blockIdx.x * 128, d0 = blockIdx.y * 128, b = blockIdx.z;
    const int wm = wid >> 2, wn = wid & 3;
    const uint32_t sbase = smem_u32(smem);

    {
        const char* srcs[4] = {
            (const char*)(g_sbhi + ((size_t)b * Tc + t0) * 32),
            (const char*)(g_sblo + ((size_t)b * Tc + t0) * 32),
            (const char*)(g_Zthi + ((size_t)b * 1024 + d0) * 32),
            (const char*)(g_Ztlo + ((size_t)b * 1024 + d0) * 32) };
#pragma unroll
        for (int a = 0; a < 4; a++) {
#pragma unroll
            for (int i = 0; i < 2; i++) {
                int e = tid + i * 256;
                int r = e >> 2, c = e & 3;
                uint4 v = *(const uint4*)(srcs[a] + (size_t)r * 64 + c * 16);
                *(uint4*)(smem + a * TILE_B + r * RB + c * 16) = v;
            }
        }
    }
    __syncthreads();

    float acc[4][4][4];
#pragma unroll
    for (int i = 0; i < 4; i++)
#pragma unroll
        for (int j = 0; j < 4; j++)
#pragma unroll
            for (int q = 0; q < 4; q++) acc[i][j][q] = 0.f;

#pragma unroll
    for (int ks = 0; ks < 2; ks++) {
        uint32_t rah[4][4], ral[4][4];
#pragma unroll
        for (int mf = 0; mf < 4; mf++) {
            int r = wm * 64 + mf * 16 + (lane & 15);
            uint32_t ad = sbase + r * RB + ks * 32 + ((lane >> 4) & 1) * 16;
            asm volatile("ldmatrix.sync.aligned.m8n8.x4.shared.b16 {%0,%1,%2,%3},[%4];"
                : "=r"(rah[mf][0]), "=r"(rah[mf][1]), "=r"(rah[mf][2]), "=r"(rah[mf][3])
                : "r"(ad));
            asm volatile("ldmatrix.sync.aligned.m8n8.x4.shared.b16 {%0,%1,%2,%3},[%4];"
                : "=r"(ral[mf][0]), "=r"(ral[mf][1]), "=r"(ral[mf][2]), "=r"(ral[mf][3])
                : "r"(ad + TILE_B));
        }
        uint32_t rbh[2][4], rbl[2][4];
#pragma unroll
        for (int np = 0; np < 2; np++) {
            int r = wn * 32 + (np * 2 + (lane >> 4)) * 8 + (lane & 7);
            uint32_t bd = sbase + 2 * TILE_B + r * RB + ks * 32 + ((lane >> 3) & 1) * 16;
            asm volatile("ldmatrix.sync.aligned.m8n8.x4.shared.b16 {%0,%1,%2,%3},[%4];"
                : "=r"(rbh[np][0]), "=r"(rbh[np][1]), "=r"(rbh[np][2]), "=r"(rbh[np][3])
                : "r"(bd));
            asm volatile("ldmatrix.sync.aligned.m8n8.x4.shared.b16 {%0,%1,%2,%3},[%4];"
                : "=r"(rbl[np][0]), "=r"(rbl[np][1]), "=r"(rbl[np][2]), "=r"(rbl[np][3])
                : "r"(bd + TILE_B));
        }
#pragma unroll
        for (int mf = 0; mf < 4; mf++)
#pragma unroll
            for (int nf = 0; nf < 4; nf++)
                MMA_OP(acc[mf][nf], rah[mf], rbh[nf >> 1][(nf & 1) * 2],
                       rbh[nf >> 1][(nf & 1) * 2 + 1]);
#pragma unroll
        for (int mf = 0; mf < 4; mf++)
#pragma unroll
            for (int nf = 0; nf < 4; nf++)
                MMA_OP(acc[mf][nf], rah[mf], rbl[nf >> 1][(nf & 1) * 2],
                       rbl[nf >> 1][(nf & 1) * 2 + 1]);
#pragma unroll
        for (int mf = 0; mf < 4; mf++)
#pragma unroll
            for (int nf = 0; nf < 4; nf++)
                MMA_OP(acc[mf][nf], ral[mf], rbh[nf >> 1][(nf & 1) * 2],
                       rbh[nf >> 1][(nf & 1) * 2 + 1]);
    }

    const int mrow = lane >> 2, ncol = (lane & 3) * 2;
#pragma unroll
    for (int mf = 0; mf < 4; mf++) {
#pragma unroll
        for (int nf = 0; nf < 4; nf++) {
            int r  = t0 + wm * 64 + mf * 16 + mrow;
            int cc = d0 + wn * 32 + nf * 8 + ncol;
            *(float2*)(out + ((size_t)b * Tc + r) * Dc + cc) =
                make_float2(acc[mf][nf][0], acc[mf][nf][1]);
            *(float2*)(out + ((size_t)b * Tc + r + 8) * Dc + cc) =
                make_float2(acc[mf][nf][2], acc[mf][nf][3]);
        }
    }
}

// ---------------------------------------------------------------------------
// Launch
// ---------------------------------------------------------------------------
extern "C" void kernel_launch(void* const* d_in, const int* in_sizes, int n_in,
                              void* d_out, int out_size)
{
    const float* x    = (const float*)d_in[0];
    const float* sb   = (const float*)d_in[1];
    const float* Wqkv = (const float*)d_in[2];
    const float* Wout = (const float*)d_in[3];
    const float* a    = (const float*)d_in[4];
    const float* b    = (const float*)d_in[5];
    const float* W1   = (const float*)d_in[6];
    const float* b1   = (const float*)d_in[7];
    const float* W2   = (const float*)d_in[8];
    const float* b2   = (const float*)d_in[9];
    const float* filt = (const float*)d_in[10];

    float* out       = (float*)d_out;
    float* out_pulse = out + (size_t)Bc * Tc * Dc;
    float* out_resp  = out_pulse + Bc * Hc;

    float *pspec_p, *pZp;
    cudaGetSymbolAddress((void**)&pspec_p, g_spec_p);
    cudaGetSymbolAddress((void**)&pZp, g_Zp);
    __nv_bfloat16 *pxshi, *pxslo, *pwqhi, *pwqlo, *pwohi, *pwolo, *pwshi, *pwslo;
    cudaGetSymbolAddress((void**)&pxshi, g_xshi);
    cudaGetSymbolAddress((void**)&pxslo, g_xslo);
    cudaGetSymbolAddress((void**)&pwqhi, g_wqhi);
    cudaGetSymbolAddress((void**)&pwqlo, g_wqlo);
    cudaGetSymbolAddress((void**)&pwohi, g_wohi);
    cudaGetSymbolAddress((void**)&pwolo, g_wolo);
    cudaGetSymbolAddress((void**)&pwshi, g_wshi);
    cudaGetSymbolAddress((void**)&pwslo, g_wslo);

    const int GEMM_SMEM = 2 * STAGE_B;
    cudaFuncSetAttribute(gemm_mma_sk, cudaFuncAttributeMaxDynamicSharedMemorySize,
                         GEMM_SMEM);

    // 0) split weights to bf16 hi/lo
    split_w_kernel<<<(1024 * 1024 + 255) / 256, 256>>>(Wqkv, Wout);

    // 1) xs partials (+ sb split) + reduce (-> xs bf16, xm fp32)
    xs_part_kernel<<<dim3(Bc, NS1), 256>>>(x, sb);
    reduce_xs_xm<<<(32768 + 1024 + 255) / 256, 256>>>();

    // 2) spec partials [HMMA split-K 8] ++ qm GEMV fused
    gemm_mma_sk<<<24 * SKS + 512, 256, GEMM_SMEM>>>(
        pxshi, pxslo, pwqhi, pwqlo, pspec_p, 3072, 1024 / SKS, 24 * SKS, Wqkv);

    // 3) spec reduce + soliton + ws2 split + pulse MLP
    soliton_pulse_kernel<<<128 + 64, 256>>>(a, b, filt, W1, b1, W2, b2,
                                            out_resp, out_pulse);

    // 4) Z partials [HMMA split-K 16] + reduce -> Zt bf16
    gemm_mma_sk<<<8 * SKZ, 256, GEMM_SMEM>>>(
        pwshi, pwslo, pwohi, pwolo, pZp, 1024, 1024 / SKZ, 8 * SKZ, Wqkv);
    reduce_Zt<<<(32768 + 255) / 256, 256>>>();

    // 5) out = sb @ Zt^T [HMMA, K=32]
    out_mma_kernel<<<dim3(Tc / 128, Dc / 128, Bc), 256>>>(out);
}